// round 10
// baseline (speedup 1.0000x reference)
#include <cuda_runtime.h>
#include <cstdint>

// ---------------------------------------------------------------------------
// XPool cross-modal attention, GB300 round 10: mma.sync tf32 + cp.async.
// CTA tile 64x128 (8 warps x 32x32) -> doubled grids, true 2 CTAs/SM
// (16 warps/SM) on every GEMM. V-transpose fused into projection epilogue.
// ---------------------------------------------------------------------------

#define EMBED 512
#define HEADS 2
#define HDIM  256
#define TTOK  4096
#define VTOK  768
#define FR    12
#define NV    64

#define APAD   36                       // smem row pitch in words
#define STG_WA (64  * APAD)             // A stage words (2304)
#define STG_WB (128 * APAD)             // B stage words (4608)
#define NSTAGE 3
#define SMEM_BYTES (NSTAGE * (STG_WA + STG_WB) * 4)   // 82944

// ------------------------------- scratch ----------------------------------
__device__ float g_tn  [TTOK*EMBED];
__device__ float g_vn  [VTOK*EMBED];
__device__ float g_q   [TTOK*EMBED];
__device__ float g_k   [VTOK*EMBED];
__device__ float g_vt  [EMBED*VTOK];
__device__ float g_s   [HEADS*TTOK*VTOK];
__device__ float g_attn[TTOK*EMBED];
__device__ float g_opre[TTOK*EMBED];
__device__ float g_o   [TTOK*EMBED];
__device__ float g_or  [TTOK*EMBED];
__device__ float g_lin [TTOK*EMBED];
__device__ float g_wqr [EMBED*EMBED];
__device__ float g_wkr [EMBED*EMBED];
__device__ float g_wvr [EMBED*EMBED];
__device__ float g_wor [EMBED*EMBED];
__device__ float g_wlr [EMBED*EMBED];

__device__ __forceinline__ uint32_t f2tf32(float x) {
    uint32_t u;
    asm("cvt.rna.tf32.f32 %0, %1;" : "=r"(u) : "f"(x));
    return u;
}
__device__ __forceinline__ float roundtf(float x) {
    return __uint_as_float(f2tf32(x));
}

#define CP16(dst, src) \
    asm volatile("cp.async.cg.shared.global [%0], [%1], 16;" \
        :: "r"(dst), "l"(src) : "memory")
#define CP_COMMIT() asm volatile("cp.async.commit_group;" ::: "memory")
#define CP_WAIT1()  asm volatile("cp.async.wait_group 1;" ::: "memory")
#define CP_WAIT0()  asm volatile("cp.async.wait_group 0;" ::: "memory")

// ---------------------------------------------------------------------------
// 64x128 NT tf32 GEMM tile, inputs pre-rounded tf32 in gmem, BK=32, 3 stages.
// 8 warps as 2 row x 4 col, warp tile 32x32.
// writeMode: 0 = normal C[i,j]; 1 = rounded C[i,j]; 2 = rounded transposed
// (C treated as [N][ldc], element [j][i]).
// ---------------------------------------------------------------------------
__device__ __forceinline__ void gemm_tile_body(
    const float* __restrict__ A, int lda,
    const float* __restrict__ B, int ldb,
    float* __restrict__ C, int ldc,
    const float* __restrict__ bias,
    float alpha, int K, int bm, int bn, int writeMode)
{
    extern __shared__ uint32_t sm[];
    uint32_t* Asw = sm;                       // [NSTAGE][64][APAD]
    uint32_t* Bsw = sm + NSTAGE * STG_WA;     // [NSTAGE][128][APAD]

    const int tid  = threadIdx.x;
    const int lane = tid & 31;
    const int warp = tid >> 5;
    const int wm   = (warp >> 2) * 32;        // 2 row-warps
    const int wn   = (warp & 3) * 32;         // 4 col-warps
    const int gid  = lane >> 2;
    const int tig  = lane & 3;

    // producers: A 64 rows x 32k, 2 CP16/thread; B 128 rows x 32k, 4 CP16.
    const int parow = tid & 63;
    const int pakc  = (tid >> 6) * 8;         // 0,8,16,24
    const int pbrow = tid & 127;
    const int pbkc  = (tid >> 7) * 16;        // 0,16
    const float* Ap = A + (size_t)(bm + parow) * lda + pakc;
    const float* Bp = B + (size_t)(bn + pbrow) * ldb + pbkc;

    const uint32_t aBase = (uint32_t)__cvta_generic_to_shared(Asw)
                         + (uint32_t)(parow * APAD + pakc) * 4u;
    const uint32_t bBase = (uint32_t)__cvta_generic_to_shared(Bsw)
                         + (uint32_t)(pbrow * APAD + pbkc) * 4u;

    float acc[2][4][4];
#pragma unroll
    for (int mi = 0; mi < 2; mi++)
#pragma unroll
        for (int ni = 0; ni < 4; ni++)
#pragma unroll
            for (int r = 0; r < 4; r++) acc[mi][ni][r] = 0.0f;

    const int nsteps = K / 32;

#pragma unroll
    for (int s = 0; s < NSTAGE - 1; s++) {
        const uint32_t ad = aBase + (uint32_t)(s * STG_WA) * 4u;
        const uint32_t bd = bBase + (uint32_t)(s * STG_WB) * 4u;
        CP16(ad,      Ap + s * 32);
        CP16(ad + 16, Ap + s * 32 + 4);
#pragma unroll
        for (int c = 0; c < 4; c++)
            CP16(bd + c * 16, Bp + s * 32 + c * 4);
        CP_COMMIT();
    }

    int cur = 0;
#pragma unroll 1
    for (int step = 0; step < nsteps; step++) {
        CP_WAIT1();
        __syncthreads();

        const uint32_t* Ac = Asw + cur * STG_WA;
        const uint32_t* Bc = Bsw + cur * STG_WB;

#pragma unroll
        for (int kk = 0; kk < 4; kk++) {
            const int kb = kk * 8;
            uint32_t af[2][4];
#pragma unroll
            for (int mi = 0; mi < 2; mi++) {
                const int r0 = (wm + mi * 16 + gid) * APAD;
                af[mi][0] = Ac[r0 + kb + tig];
                af[mi][1] = Ac[r0 + 8 * APAD + kb + tig];
                af[mi][2] = Ac[r0 + kb + tig + 4];
                af[mi][3] = Ac[r0 + 8 * APAD + kb + tig + 4];
            }
            uint32_t bf[4][2];
#pragma unroll
            for (int ni = 0; ni < 4; ni++) {
                const int n0 = (wn + ni * 8 + gid) * APAD;
                bf[ni][0] = Bc[n0 + kb + tig];
                bf[ni][1] = Bc[n0 + kb + tig + 4];
            }
#pragma unroll
            for (int mi = 0; mi < 2; mi++)
#pragma unroll
                for (int ni = 0; ni < 4; ni++) {
                    asm("mma.sync.aligned.m16n8k8.row.col.f32.tf32.tf32.f32 "
                        "{%0,%1,%2,%3}, {%4,%5,%6,%7}, {%8,%9}, {%0,%1,%2,%3};"
                        : "+f"(acc[mi][ni][0]), "+f"(acc[mi][ni][1]),
                          "+f"(acc[mi][ni][2]), "+f"(acc[mi][ni][3])
                        : "r"(af[mi][0]), "r"(af[mi][1]),
                          "r"(af[mi][2]), "r"(af[mi][3]),
                          "r"(bf[ni][0]), "r"(bf[ni][1]));
                }
        }

        const int pf = step + NSTAGE - 1;
        if (pf < nsteps) {
            int ps = cur + NSTAGE - 1; if (ps >= NSTAGE) ps -= NSTAGE;
            const uint32_t ad = aBase + (uint32_t)(ps * STG_WA) * 4u;
            const uint32_t bd = bBase + (uint32_t)(ps * STG_WB) * 4u;
            CP16(ad,      Ap + pf * 32);
            CP16(ad + 16, Ap + pf * 32 + 4);
#pragma unroll
            for (int c = 0; c < 4; c++)
                CP16(bd + c * 16, Bp + pf * 32 + c * 4);
        }
        CP_COMMIT();
        cur = (cur + 1 == NSTAGE) ? 0 : cur + 1;
    }
    CP_WAIT0();

    // epilogue
#pragma unroll
    for (int mi = 0; mi < 2; mi++) {
        const int r0 = bm + wm + mi * 16 + gid;
#pragma unroll
        for (int ni = 0; ni < 4; ni++) {
            const int c0 = bn + wn + ni * 8 + tig * 2;
            float bx = 0.0f, by = 0.0f;
            if (bias) { bx = bias[c0]; by = bias[c0 + 1]; }
            float2 v0, v1;
            v0.x = alpha * acc[mi][ni][0] + bx;
            v0.y = alpha * acc[mi][ni][1] + by;
            v1.x = alpha * acc[mi][ni][2] + bx;
            v1.y = alpha * acc[mi][ni][3] + by;
            if (writeMode == 0) {
                *(float2*)(C + (size_t)r0 * ldc + c0)       = v0;
                *(float2*)(C + (size_t)(r0 + 8) * ldc + c0) = v1;
            } else if (writeMode == 1) {
                v0.x = roundtf(v0.x); v0.y = roundtf(v0.y);
                v1.x = roundtf(v1.x); v1.y = roundtf(v1.y);
                *(float2*)(C + (size_t)r0 * ldc + c0)       = v0;
                *(float2*)(C + (size_t)(r0 + 8) * ldc + c0) = v1;
            } else {
                // transposed rounded store: C[(c)][r]
                C[(size_t)(c0    ) * ldc + r0    ] = roundtf(v0.x);
                C[(size_t)(c0 + 1) * ldc + r0    ] = roundtf(v0.y);
                C[(size_t)(c0    ) * ldc + r0 + 8] = roundtf(v1.x);
                C[(size_t)(c0 + 1) * ldc + r0 + 8] = roundtf(v1.y);
            }
        }
    }
}

__global__ __launch_bounds__(256, 2) void mma_gemm(
    const float* __restrict__ A, int lda, long zA,
    const float* __restrict__ B, int ldb, long zB,
    float* __restrict__ C, int ldc, long zC,
    const float* __restrict__ bias, long zBias,
    float alpha, int K, int writeMode)
{
    A += (long)blockIdx.z * zA;
    B += (long)blockIdx.z * zB;
    C += (long)blockIdx.z * zC;
    if (bias) bias += (long)blockIdx.z * zBias;
    gemm_tile_body(A, lda, B, ldb, C, ldc, bias, alpha, K,
                   blockIdx.y * 64, blockIdx.x * 128, writeMode);
}

// Dense projection launch: 256 Q tiles, 48 K tiles, 48 V tiles = 352 CTAs.
// Q,K write rounded normal; V writes rounded TRANSPOSED into vt[512][768].
__global__ __launch_bounds__(256, 2) void proj3_gemm(
    const float* __restrict__ tn, const float* __restrict__ vn,
    const float* __restrict__ Wq, const float* __restrict__ Wk,
    const float* __restrict__ Wv,
    const float* __restrict__ bq, const float* __restrict__ bk,
    const float* __restrict__ bv,
    float* __restrict__ q, float* __restrict__ k, float* __restrict__ vt)
{
    const int idx = blockIdx.x;
    int z, local;
    if (idx < 256)      { z = 0; local = idx; }
    else if (idx < 304) { z = 1; local = idx - 256; }
    else                { z = 2; local = idx - 304; }
    const int bn = (local & 3) * 128;
    const int bm = (local >> 2) * 64;
    const float* A = (z == 0) ? tn : vn;
    const float* B = (z == 0) ? Wq : (z == 1) ? Wk : Wv;
    const float* bias = (z == 0) ? bq : (z == 1) ? bk : bv;
    if (z == 2) {
        gemm_tile_body(A, EMBED, B, EMBED, vt, VTOK, bias, 1.0f, EMBED,
                       bm, bn, 2);
    } else {
        float* C = (z == 0) ? q : k;
        gemm_tile_body(A, EMBED, B, EMBED, C, EMBED, bias, 1.0f, EMBED,
                       bm, bn, 1);
    }
}

// ---------------------------------------------------------------------------
// Round 5 weight matrices to tf32 (one shot).
// ---------------------------------------------------------------------------
__global__ __launch_bounds__(256) void roundw_kernel(
    const float* __restrict__ w0, const float* __restrict__ w1,
    const float* __restrict__ w2, const float* __restrict__ w3,
    const float* __restrict__ w4,
    float* __restrict__ o0, float* __restrict__ o1,
    float* __restrict__ o2, float* __restrict__ o3,
    float* __restrict__ o4)
{
    const int i = blockIdx.x * 256 + threadIdx.x;
    const int z = blockIdx.y;
    const float* w = (z == 0) ? w0 : (z == 1) ? w1 : (z == 2) ? w2
                   : (z == 3) ? w3 : w4;
    float* o = (z == 0) ? o0 : (z == 1) ? o1 : (z == 2) ? o2
             : (z == 3) ? o3 : o4;
    float4 x = *(const float4*)(w + i * 4);
    float4 y;
    y.x = roundtf(x.x); y.y = roundtf(x.y);
    y.z = roundtf(x.z); y.w = roundtf(x.w);
    *(float4*)(o + i * 4) = y;
}

// ---------------------------------------------------------------------------
// LayerNorm. round_main rounds the primary output; out_r = extra rounded copy.
// ---------------------------------------------------------------------------
__global__ __launch_bounds__(128) void ln_kernel(
    const float* __restrict__ x, const float* __restrict__ addx,
    const float* __restrict__ g, const float* __restrict__ b,
    float* __restrict__ out, float* __restrict__ out_r, int round_main)
{
    const int row = blockIdx.x;
    const int t = threadIdx.x;
    const float* xr = x + (size_t)row * EMBED;

    float v[4];
#pragma unroll
    for (int i = 0; i < 4; i++) {
        float val = xr[t + i * 128];
        if (addx) val += addx[(size_t)row * EMBED + t + i * 128];
        v[i] = val;
    }
    float s  = v[0] + v[1] + v[2] + v[3];
    float s2 = v[0]*v[0] + v[1]*v[1] + v[2]*v[2] + v[3]*v[3];
#pragma unroll
    for (int o = 16; o > 0; o >>= 1) {
        s  += __shfl_xor_sync(0xffffffffu, s,  o);
        s2 += __shfl_xor_sync(0xffffffffu, s2, o);
    }
    __shared__ float ss[4], ss2[4];
    const int w = t >> 5, l = t & 31;
    if (l == 0) { ss[w] = s; ss2[w] = s2; }
    __syncthreads();
    s  = ss[0] + ss[1] + ss[2] + ss[3];
    s2 = ss2[0] + ss2[1] + ss2[2] + ss2[3];

    const float mu   = s * (1.0f / EMBED);
    const float var  = s2 * (1.0f / EMBED) - mu * mu;
    const float rstd = rsqrtf(var + 1e-5f);
#pragma unroll
    for (int i = 0; i < 4; i++) {
        const int c = t + i * 128;
        float y = (v[i] - mu) * rstd * g[c] + b[c];
        out[(size_t)row * EMBED + c] = round_main ? roundtf(y) : y;
        if (out_r) out_r[(size_t)row * EMBED + c] = roundtf(y);
    }
}

// ---------------------------------------------------------------------------
// Per-(video,head,token) softmax over 12 frames; output tf32-rounded.
// ---------------------------------------------------------------------------
__global__ __launch_bounds__(256) void softmax_kernel(float* __restrict__ S, int ngroups)
{
    const int g = blockIdx.x * blockDim.x + threadIdx.x;
    if (g >= ngroups) return;
    float* p = S + (size_t)g * FR;
    float v[FR];
    float m = -3.0e38f;
#pragma unroll
    for (int i = 0; i < FR; i++) { v[i] = p[i]; m = fmaxf(m, v[i]); }
    float sum = 0.0f;
#pragma unroll
    for (int i = 0; i < FR; i++) { v[i] = __expf(v[i] - m); sum += v[i]; }
    const float inv = 1.0f / sum;
#pragma unroll
    for (int i = 0; i < FR; i++) p[i] = roundtf(v[i] * inv);
}

// ---------------------------------------------------------------------------
extern "C" void kernel_launch(void* const* d_in, const int* in_sizes, int n_in,
                              void* d_out, int out_size)
{
    const float* text  = (const float*)d_in[0];
    const float* video = (const float*)d_in[1];
    const float* ln1_g = (const float*)d_in[2];
    const float* ln1_b = (const float*)d_in[3];
    const float* Wq = (const float*)d_in[4];
    const float* bq = (const float*)d_in[5];
    const float* Wk = (const float*)d_in[6];
    const float* bk = (const float*)d_in[7];
    const float* Wv = (const float*)d_in[8];
    const float* bv = (const float*)d_in[9];
    const float* Wo = (const float*)d_in[10];
    const float* bo = (const float*)d_in[11];
    const float* Wl = (const float*)d_in[12];
    const float* bl = (const float*)d_in[13];
    const float* ln2_g = (const float*)d_in[14];
    const float* ln2_b = (const float*)d_in[15];
    const float* ln3_g = (const float*)d_in[16];
    const float* ln3_b = (const float*)d_in[17];
    float* out = (float*)d_out;

    cudaFuncSetAttribute(mma_gemm,
        cudaFuncAttributeMaxDynamicSharedMemorySize, SMEM_BYTES);
    cudaFuncSetAttribute(proj3_gemm,
        cudaFuncAttributeMaxDynamicSharedMemorySize, SMEM_BYTES);

    float *tn, *vn, *q, *k, *vt, *s, *attn, *opre, *o, *orr, *lin;
    float *wqr, *wkr, *wvr, *wor, *wlr;
    cudaGetSymbolAddress((void**)&tn,   g_tn);
    cudaGetSymbolAddress((void**)&vn,   g_vn);
    cudaGetSymbolAddress((void**)&q,    g_q);
    cudaGetSymbolAddress((void**)&k,    g_k);
    cudaGetSymbolAddress((void**)&vt,   g_vt);
    cudaGetSymbolAddress((void**)&s,    g_s);
    cudaGetSymbolAddress((void**)&attn, g_attn);
    cudaGetSymbolAddress((void**)&opre, g_opre);
    cudaGetSymbolAddress((void**)&o,    g_o);
    cudaGetSymbolAddress((void**)&orr,  g_or);
    cudaGetSymbolAddress((void**)&lin,  g_lin);
    cudaGetSymbolAddress((void**)&wqr,  g_wqr);
    cudaGetSymbolAddress((void**)&wkr,  g_wkr);
    cudaGetSymbolAddress((void**)&wvr,  g_wvr);
    cudaGetSymbolAddress((void**)&wor,  g_wor);
    cudaGetSymbolAddress((void**)&wlr,  g_wlr);

    // 0) round all weights to tf32 (overlaps LN1)
    roundw_kernel<<<dim3(EMBED*EMBED/1024, 5), 256>>>(
        Wq, Wk, Wv, Wo, Wl, wqr, wkr, wvr, wor, wlr);

    // 1) shared LN1 (outputs tf32-rounded)
    ln_kernel<<<TTOK, 128>>>(text,  nullptr, ln1_g, ln1_b, tn, nullptr, 1);
    ln_kernel<<<VTOK, 128>>>(video, nullptr, ln1_g, ln1_b, vn, nullptr, 1);

    // 2) Q/K/V projections (V written transposed into vt), 352 CTAs
    proj3_gemm<<<352, 256, SMEM_BYTES>>>(
        tn, vn, wqr, wkr, wvr, bq, bk, bv, q, k, vt);

    // 3) logits: S_h = Q_h @ K_h^T / 16  (768 CTAs)
    mma_gemm<<<dim3(6, 64, 2), 256, SMEM_BYTES>>>(
        q, EMBED, HDIM, k, EMBED, HDIM,
        s, VTOK, (long)TTOK * VTOK, nullptr, 0, 1.0f / 16.0f, HDIM, 0);

    // 4) per-video frame softmax (rounds output)
    softmax_kernel<<<(HEADS * TTOK * NV + 255) / 256, 256>>>(s, HEADS * TTOK * NV);

    // 5) attn_h = P_h @ V_h / 64 (rounded out; 256 CTAs)
    mma_gemm<<<dim3(2, 64, 2), 256, SMEM_BYTES>>>(
        s, VTOK, (long)TTOK * VTOK, vt, VTOK, (long)HDIM * VTOK,
        attn, EMBED, HDIM, nullptr, 0, 1.0f / 64.0f, VTOK, 1);

    // 6) output projection + LN2 (o full + rounded copy; 256 CTAs)
    mma_gemm<<<dim3(4, 64, 1), 256, SMEM_BYTES>>>(
        attn, EMBED, 0, wor, EMBED, 0, opre, EMBED, 0, bo, 0, 1.0f, EMBED, 0);
    ln_kernel<<<TTOK, 128>>>(opre, nullptr, ln2_g, ln2_b, o, orr, 0);

    // 7) linear + residual + LN3 (256 CTAs)
    mma_gemm<<<dim3(4, 64, 1), 256, SMEM_BYTES>>>(
        orr, EMBED, 0, wlr, EMBED, 0, lin, EMBED, 0, bl, 0, 1.0f, EMBED, 0);
    ln_kernel<<<TTOK, 128>>>(o, lin, ln3_g, ln3_b, out, nullptr, 0);
}

// round 11
// speedup vs baseline: 1.2041x; 1.2041x over previous
#include <cuda_runtime.h>
#include <cstdint>

// ---------------------------------------------------------------------------
// XPool cross-modal attention, GB300 round 11: R8 config restored
// (128x128 CTA tile, BK=16, 4-stage cp.async, 2 CTAs/SM) +
// V-transpose fused into projection epilogue + dense 176-CTA proj grid.
// ---------------------------------------------------------------------------

#define EMBED 512
#define HEADS 2
#define HDIM  256
#define TTOK  4096
#define VTOK  768
#define FR    12
#define NV    64

#define APAD   20                     // smem row pitch in words
#define STG_W  (128 * APAD)           // words per stage per matrix (2560)
#define NSTAGE 4
#define SMEM_BYTES (2 * NSTAGE * STG_W * 4)   // 81920

// ------------------------------- scratch ----------------------------------
__device__ float g_tn  [TTOK*EMBED];
__device__ float g_vn  [VTOK*EMBED];
__device__ float g_q   [TTOK*EMBED];
__device__ float g_k   [VTOK*EMBED];
__device__ float g_vt  [EMBED*VTOK];          // V transposed [512][768]
__device__ float g_s   [HEADS*TTOK*VTOK];
__device__ float g_attn[TTOK*EMBED];
__device__ float g_opre[TTOK*EMBED];
__device__ float g_o   [TTOK*EMBED];
__device__ float g_or  [TTOK*EMBED];
__device__ float g_lin [TTOK*EMBED];
__device__ float g_wqr [EMBED*EMBED];
__device__ float g_wkr [EMBED*EMBED];
__device__ float g_wvr [EMBED*EMBED];
__device__ float g_wor [EMBED*EMBED];
__device__ float g_wlr [EMBED*EMBED];

__device__ __forceinline__ uint32_t f2tf32(float x) {
    uint32_t u;
    asm("cvt.rna.tf32.f32 %0, %1;" : "=r"(u) : "f"(x));
    return u;
}
__device__ __forceinline__ float roundtf(float x) {
    return __uint_as_float(f2tf32(x));
}

#define CP16(dst, src) \
    asm volatile("cp.async.cg.shared.global [%0], [%1], 16;" \
        :: "r"(dst), "l"(src) : "memory")
#define CP_COMMIT() asm volatile("cp.async.commit_group;" ::: "memory")
#define CP_WAIT2()  asm volatile("cp.async.wait_group 2;" ::: "memory")
#define CP_WAIT0()  asm volatile("cp.async.wait_group 0;" ::: "memory")

// ---------------------------------------------------------------------------
// 128x128 NT tf32 GEMM, inputs pre-rounded to tf32 in gmem.
// writeMode: 0 = C[i,j]; 1 = rounded C[i,j]; 2 = rounded transposed C[j][i].
// ---------------------------------------------------------------------------
__device__ __forceinline__ void gemm_tile_body(
    const float* __restrict__ A, int lda,
    const float* __restrict__ B, int ldb,
    float* __restrict__ C, int ldc,
    const float* __restrict__ bias,
    float alpha, int K, int bm, int bn, int writeMode)
{
    extern __shared__ uint32_t sm[];
    uint32_t* Asw = sm;                       // [NSTAGE][128][APAD]
    uint32_t* Bsw = sm + NSTAGE * STG_W;

    const int tid  = threadIdx.x;
    const int lane = tid & 31;
    const int warp = tid >> 5;
    const int wm   = (warp >> 1) * 32;
    const int wn   = (warp & 1) * 64;
    const int gid  = lane >> 2;
    const int tig  = lane & 3;

    const int prow = tid & 127;
    const int pkc  = (tid >> 7) * 8;
    const float* Ap = A + (size_t)(bm + prow) * lda + pkc;
    const float* Bp = B + (size_t)(bn + prow) * ldb + pkc;

    const uint32_t aBase = (uint32_t)__cvta_generic_to_shared(Asw)
                         + (uint32_t)(prow * APAD + pkc) * 4u;
    const uint32_t bBase = (uint32_t)__cvta_generic_to_shared(Bsw)
                         + (uint32_t)(prow * APAD + pkc) * 4u;

    float acc[2][8][4];
#pragma unroll
    for (int mi = 0; mi < 2; mi++)
#pragma unroll
        for (int ni = 0; ni < 8; ni++)
#pragma unroll
            for (int r = 0; r < 4; r++) acc[mi][ni][r] = 0.0f;

    const int nsteps = K / 16;

#pragma unroll
    for (int s = 0; s < NSTAGE - 1; s++) {
        const uint32_t ad = aBase + (uint32_t)(s * STG_W) * 4u;
        const uint32_t bd = bBase + (uint32_t)(s * STG_W) * 4u;
        CP16(ad,      Ap + s * 16);
        CP16(ad + 16, Ap + s * 16 + 4);
        CP16(bd,      Bp + s * 16);
        CP16(bd + 16, Bp + s * 16 + 4);
        CP_COMMIT();
    }

#pragma unroll 1
    for (int step = 0; step < nsteps; step++) {
        const int cur = step & (NSTAGE - 1);
        CP_WAIT2();
        __syncthreads();

        const uint32_t* Ac = Asw + cur * STG_W;
        const uint32_t* Bc = Bsw + cur * STG_W;

#pragma unroll
        for (int kk = 0; kk < 2; kk++) {
            const int kb = kk * 8;
            uint32_t af[2][4];
#pragma unroll
            for (int mi = 0; mi < 2; mi++) {
                const int r0 = (wm + mi * 16 + gid) * APAD;
                af[mi][0] = Ac[r0 + kb + tig];
                af[mi][1] = Ac[r0 + 8 * APAD + kb + tig];
                af[mi][2] = Ac[r0 + kb + tig + 4];
                af[mi][3] = Ac[r0 + 8 * APAD + kb + tig + 4];
            }
            uint32_t bf[8][2];
#pragma unroll
            for (int ni = 0; ni < 8; ni++) {
                const int n0 = (wn + ni * 8 + gid) * APAD;
                bf[ni][0] = Bc[n0 + kb + tig];
                bf[ni][1] = Bc[n0 + kb + tig + 4];
            }
#pragma unroll
            for (int mi = 0; mi < 2; mi++)
#pragma unroll
                for (int ni = 0; ni < 8; ni++) {
                    asm("mma.sync.aligned.m16n8k8.row.col.f32.tf32.tf32.f32 "
                        "{%0,%1,%2,%3}, {%4,%5,%6,%7}, {%8,%9}, {%0,%1,%2,%3};"
                        : "+f"(acc[mi][ni][0]), "+f"(acc[mi][ni][1]),
                          "+f"(acc[mi][ni][2]), "+f"(acc[mi][ni][3])
                        : "r"(af[mi][0]), "r"(af[mi][1]),
                          "r"(af[mi][2]), "r"(af[mi][3]),
                          "r"(bf[ni][0]), "r"(bf[ni][1]));
                }
        }

        const int pf = step + NSTAGE - 1;
        if (pf < nsteps) {
            const int ps = pf & (NSTAGE - 1);
            const uint32_t ad = aBase + (uint32_t)(ps * STG_W) * 4u;
            const uint32_t bd = bBase + (uint32_t)(ps * STG_W) * 4u;
            CP16(ad,      Ap + pf * 16);
            CP16(ad + 16, Ap + pf * 16 + 4);
            CP16(bd,      Bp + pf * 16);
            CP16(bd + 16, Bp + pf * 16 + 4);
        }
        CP_COMMIT();
    }
    CP_WAIT0();

    // epilogue
#pragma unroll
    for (int mi = 0; mi < 2; mi++) {
        const int r0 = bm + wm + mi * 16 + gid;
#pragma unroll
        for (int ni = 0; ni < 8; ni++) {
            const int c0 = bn + wn + ni * 8 + tig * 2;
            float bx = 0.0f, by = 0.0f;
            if (bias) { bx = bias[c0]; by = bias[c0 + 1]; }
            float2 v0, v1;
            v0.x = alpha * acc[mi][ni][0] + bx;
            v0.y = alpha * acc[mi][ni][1] + by;
            v1.x = alpha * acc[mi][ni][2] + bx;
            v1.y = alpha * acc[mi][ni][3] + by;
            if (writeMode == 0) {
                *(float2*)(C + (size_t)r0 * ldc + c0)       = v0;
                *(float2*)(C + (size_t)(r0 + 8) * ldc + c0) = v1;
            } else if (writeMode == 1) {
                v0.x = roundtf(v0.x); v0.y = roundtf(v0.y);
                v1.x = roundtf(v1.x); v1.y = roundtf(v1.y);
                *(float2*)(C + (size_t)r0 * ldc + c0)       = v0;
                *(float2*)(C + (size_t)(r0 + 8) * ldc + c0) = v1;
            } else {
                // rounded transposed store: C[col][row], ldc = row count dim
                C[(size_t)(c0    ) * ldc + r0    ] = roundtf(v0.x);
                C[(size_t)(c0 + 1) * ldc + r0    ] = roundtf(v0.y);
                C[(size_t)(c0    ) * ldc + r0 + 8] = roundtf(v1.x);
                C[(size_t)(c0 + 1) * ldc + r0 + 8] = roundtf(v1.y);
            }
        }
    }
}

__global__ __launch_bounds__(256, 2) void mma_gemm(
    const float* __restrict__ A, int lda, long zA,
    const float* __restrict__ B, int ldb, long zB,
    float* __restrict__ C, int ldc, long zC,
    const float* __restrict__ bias, long zBias,
    float alpha, int K, int writeMode)
{
    A += (long)blockIdx.z * zA;
    B += (long)blockIdx.z * zB;
    C += (long)blockIdx.z * zC;
    if (bias) bias += (long)blockIdx.z * zBias;
    gemm_tile_body(A, lda, B, ldb, C, ldc, bias, alpha, K,
                   blockIdx.y * 128, blockIdx.x * 128, writeMode);
}

// Dense projection launch: 128 Q tiles, 24 K tiles, 24 V tiles = 176 CTAs.
// Q,K rounded normal; V written rounded TRANSPOSED into vt[512][768].
__global__ __launch_bounds__(256, 2) void proj3_gemm(
    const float* __restrict__ tn, const float* __restrict__ vn,
    const float* __restrict__ Wq, const float* __restrict__ Wk,
    const float* __restrict__ Wv,
    const float* __restrict__ bq, const float* __restrict__ bk,
    const float* __restrict__ bv,
    float* __restrict__ q, float* __restrict__ k, float* __restrict__ vt)
{
    const int idx = blockIdx.x;
    int z, local;
    if (idx < 128)      { z = 0; local = idx; }
    else if (idx < 152) { z = 1; local = idx - 128; }
    else                { z = 2; local = idx - 152; }
    const int bn = (local & 3) * 128;
    const int bm = (local >> 2) * 128;
    const float* A = (z == 0) ? tn : vn;
    const float* B = (z == 0) ? Wq : (z == 1) ? Wk : Wv;
    const float* bias = (z == 0) ? bq : (z == 1) ? bk : bv;
    if (z == 2) {
        gemm_tile_body(A, EMBED, B, EMBED, vt, VTOK, bias, 1.0f, EMBED,
                       bm, bn, 2);
    } else {
        float* C = (z == 0) ? q : k;
        gemm_tile_body(A, EMBED, B, EMBED, C, EMBED, bias, 1.0f, EMBED,
                       bm, bn, 1);
    }
}

// ---------------------------------------------------------------------------
// Round 5 weight matrices to tf32 (one shot, overlaps LN1).
// ---------------------------------------------------------------------------
__global__ __launch_bounds__(256) void roundw_kernel(
    const float* __restrict__ w0, const float* __restrict__ w1,
    const float* __restrict__ w2, const float* __restrict__ w3,
    const float* __restrict__ w4,
    float* __restrict__ o0, float* __restrict__ o1,
    float* __restrict__ o2, float* __restrict__ o3,
    float* __restrict__ o4)
{
    const int i = blockIdx.x * 256 + threadIdx.x;
    const int z = blockIdx.y;
    const float* w = (z == 0) ? w0 : (z == 1) ? w1 : (z == 2) ? w2
                   : (z == 3) ? w3 : w4;
    float* o = (z == 0) ? o0 : (z == 1) ? o1 : (z == 2) ? o2
             : (z == 3) ? o3 : o4;
    float4 x = *(const float4*)(w + i * 4);
    float4 y;
    y.x = roundtf(x.x); y.y = roundtf(x.y);
    y.z = roundtf(x.z); y.w = roundtf(x.w);
    *(float4*)(o + i * 4) = y;
}

// ---------------------------------------------------------------------------
// LayerNorm. round_main rounds the primary output; out_r = extra rounded copy.
// ---------------------------------------------------------------------------
__global__ __launch_bounds__(128) void ln_kernel(
    const float* __restrict__ x, const float* __restrict__ addx,
    const float* __restrict__ g, const float* __restrict__ b,
    float* __restrict__ out, float* __restrict__ out_r, int round_main)
{
    const int row = blockIdx.x;
    const int t = threadIdx.x;
    const float* xr = x + (size_t)row * EMBED;

    float v[4];
#pragma unroll
    for (int i = 0; i < 4; i++) {
        float val = xr[t + i * 128];
        if (addx) val += addx[(size_t)row * EMBED + t + i * 128];
        v[i] = val;
    }
    float s  = v[0] + v[1] + v[2] + v[3];
    float s2 = v[0]*v[0] + v[1]*v[1] + v[2]*v[2] + v[3]*v[3];
#pragma unroll
    for (int o = 16; o > 0; o >>= 1) {
        s  += __shfl_xor_sync(0xffffffffu, s,  o);
        s2 += __shfl_xor_sync(0xffffffffu, s2, o);
    }
    __shared__ float ss[4], ss2[4];
    const int w = t >> 5, l = t & 31;
    if (l == 0) { ss[w] = s; ss2[w] = s2; }
    __syncthreads();
    s  = ss[0] + ss[1] + ss[2] + ss[3];
    s2 = ss2[0] + ss2[1] + ss2[2] + ss2[3];

    const float mu   = s * (1.0f / EMBED);
    const float var  = s2 * (1.0f / EMBED) - mu * mu;
    const float rstd = rsqrtf(var + 1e-5f);
#pragma unroll
    for (int i = 0; i < 4; i++) {
        const int c = t + i * 128;
        float y = (v[i] - mu) * rstd * g[c] + b[c];
        out[(size_t)row * EMBED + c] = round_main ? roundtf(y) : y;
        if (out_r) out_r[(size_t)row * EMBED + c] = roundtf(y);
    }
}

// ---------------------------------------------------------------------------
// Per-(video,head,token) softmax over 12 frames; output tf32-rounded.
// ---------------------------------------------------------------------------
__global__ __launch_bounds__(256) void softmax_kernel(float* __restrict__ S, int ngroups)
{
    const int g = blockIdx.x * blockDim.x + threadIdx.x;
    if (g >= ngroups) return;
    float* p = S + (size_t)g * FR;
    float v[FR];
    float m = -3.0e38f;
#pragma unroll
    for (int i = 0; i < FR; i++) { v[i] = p[i]; m = fmaxf(m, v[i]); }
    float sum = 0.0f;
#pragma unroll
    for (int i = 0; i < FR; i++) { v[i] = __expf(v[i] - m); sum += v[i]; }
    const float inv = 1.0f / sum;
#pragma unroll
    for (int i = 0; i < FR; i++) p[i] = roundtf(v[i] * inv);
}

// ---------------------------------------------------------------------------
extern "C" void kernel_launch(void* const* d_in, const int* in_sizes, int n_in,
                              void* d_out, int out_size)
{
    const float* text  = (const float*)d_in[0];
    const float* video = (const float*)d_in[1];
    const float* ln1_g = (const float*)d_in[2];
    const float* ln1_b = (const float*)d_in[3];
    const float* Wq = (const float*)d_in[4];
    const float* bq = (const float*)d_in[5];
    const float* Wk = (const float*)d_in[6];
    const float* bk = (const float*)d_in[7];
    const float* Wv = (const float*)d_in[8];
    const float* bv = (const float*)d_in[9];
    const float* Wo = (const float*)d_in[10];
    const float* bo = (const float*)d_in[11];
    const float* Wl = (const float*)d_in[12];
    const float* bl = (const float*)d_in[13];
    const float* ln2_g = (const float*)d_in[14];
    const float* ln2_b = (const float*)d_in[15];
    const float* ln3_g = (const float*)d_in[16];
    const float* ln3_b = (const float*)d_in[17];
    float* out = (float*)d_out;

    cudaFuncSetAttribute(mma_gemm,
        cudaFuncAttributeMaxDynamicSharedMemorySize, SMEM_BYTES);
    cudaFuncSetAttribute(proj3_gemm,
        cudaFuncAttributeMaxDynamicSharedMemorySize, SMEM_BYTES);

    float *tn, *vn, *q, *k, *vt, *s, *attn, *opre, *o, *orr, *lin;
    float *wqr, *wkr, *wvr, *wor, *wlr;
    cudaGetSymbolAddress((void**)&tn,   g_tn);
    cudaGetSymbolAddress((void**)&vn,   g_vn);
    cudaGetSymbolAddress((void**)&q,    g_q);
    cudaGetSymbolAddress((void**)&k,    g_k);
    cudaGetSymbolAddress((void**)&vt,   g_vt);
    cudaGetSymbolAddress((void**)&s,    g_s);
    cudaGetSymbolAddress((void**)&attn, g_attn);
    cudaGetSymbolAddress((void**)&opre, g_opre);
    cudaGetSymbolAddress((void**)&o,    g_o);
    cudaGetSymbolAddress((void**)&orr,  g_or);
    cudaGetSymbolAddress((void**)&lin,  g_lin);
    cudaGetSymbolAddress((void**)&wqr,  g_wqr);
    cudaGetSymbolAddress((void**)&wkr,  g_wkr);
    cudaGetSymbolAddress((void**)&wvr,  g_wvr);
    cudaGetSymbolAddress((void**)&wor,  g_wor);
    cudaGetSymbolAddress((void**)&wlr,  g_wlr);

    // 0) round all weights to tf32 (overlaps LN1)
    roundw_kernel<<<dim3(EMBED*EMBED/1024, 5), 256>>>(
        Wq, Wk, Wv, Wo, Wl, wqr, wkr, wvr, wor, wlr);

    // 1) shared LN1 (outputs tf32-rounded)
    ln_kernel<<<TTOK, 128>>>(text,  nullptr, ln1_g, ln1_b, tn, nullptr, 1);
    ln_kernel<<<VTOK, 128>>>(video, nullptr, ln1_g, ln1_b, vn, nullptr, 1);

    // 2) Q/K/V projections (V written transposed into vt), 176 CTAs
    proj3_gemm<<<176, 256, SMEM_BYTES>>>(
        tn, vn, wqr, wkr, wvr, bq, bk, bv, q, k, vt);

    // 3) logits: S_h = Q_h @ K_h^T / 16 (384 CTAs)
    mma_gemm<<<dim3(6, 32, 2), 256, SMEM_BYTES>>>(
        q, EMBED, HDIM, k, EMBED, HDIM,
        s, VTOK, (long)TTOK * VTOK, nullptr, 0, 1.0f / 16.0f, HDIM, 0);

    // 4) per-video frame softmax (rounds output)
    softmax_kernel<<<(HEADS * TTOK * NV + 255) / 256, 256>>>(s, HEADS * TTOK * NV);

    // 5) attn_h = P_h @ V_h / 64 (rounded out; 128 CTAs)
    mma_gemm<<<dim3(2, 32, 2), 256, SMEM_BYTES>>>(
        s, VTOK, (long)TTOK * VTOK, vt, VTOK, (long)HDIM * VTOK,
        attn, EMBED, HDIM, nullptr, 0, 1.0f / 64.0f, VTOK, 1);

    // 6) output projection + LN2 (o full + rounded copy; 128 CTAs)
    mma_gemm<<<dim3(4, 32, 1), 256, SMEM_BYTES>>>(
        attn, EMBED, 0, wor, EMBED, 0, opre, EMBED, 0, bo, 0, 1.0f, EMBED, 0);
    ln_kernel<<<TTOK, 128>>>(opre, nullptr, ln2_g, ln2_b, o, orr, 0);

    // 7) linear + residual + LN3 (128 CTAs)
    mma_gemm<<<dim3(4, 32, 1), 256, SMEM_BYTES>>>(
        orr, EMBED, 0, wlr, EMBED, 0, lin, EMBED, 0, bl, 0, 1.0f, EMBED, 0);
    ln_kernel<<<TTOK, 128>>>(o, lin, ln3_g, ln3_b, out, nullptr, 0);
}

// round 12
// speedup vs baseline: 1.2676x; 1.0528x over previous
#include <cuda_runtime.h>
#include <cstdint>

// ---------------------------------------------------------------------------
// XPool cross-modal attention, GB300 round 12: R11 + ldmatrix fragments.
// 128x128 CTA tile, BK=16, 4-stage cp.async, 2 CTAs/SM. Fragment loads via
// ldmatrix.m8n8.x4.b16 (f32 reinterpretation): 12 LDSM/step vs 48 LDS.
// ---------------------------------------------------------------------------

#define EMBED 512
#define HEADS 2
#define HDIM  256
#define TTOK  4096
#define VTOK  768
#define FR    12
#define NV    64

#define APAD   20                     // smem row pitch in words (80B, 16B-mult)
#define STG_W  (128 * APAD)           // words per stage per matrix (2560)
#define NSTAGE 4
#define SMEM_BYTES (2 * NSTAGE * STG_W * 4)   // 81920

// ------------------------------- scratch ----------------------------------
__device__ float g_tn  [TTOK*EMBED];
__device__ float g_vn  [VTOK*EMBED];
__device__ float g_q   [TTOK*EMBED];
__device__ float g_k   [VTOK*EMBED];
__device__ float g_vt  [EMBED*VTOK];
__device__ float g_s   [HEADS*TTOK*VTOK];
__device__ float g_attn[TTOK*EMBED];
__device__ float g_opre[TTOK*EMBED];
__device__ float g_o   [TTOK*EMBED];
__device__ float g_or  [TTOK*EMBED];
__device__ float g_lin [TTOK*EMBED];
__device__ float g_wqr [EMBED*EMBED];
__device__ float g_wkr [EMBED*EMBED];
__device__ float g_wvr [EMBED*EMBED];
__device__ float g_wor [EMBED*EMBED];
__device__ float g_wlr [EMBED*EMBED];

__device__ __forceinline__ uint32_t f2tf32(float x) {
    uint32_t u;
    asm("cvt.rna.tf32.f32 %0, %1;" : "=r"(u) : "f"(x));
    return u;
}
__device__ __forceinline__ float roundtf(float x) {
    return __uint_as_float(f2tf32(x));
}

#define CP16(dst, src) \
    asm volatile("cp.async.cg.shared.global [%0], [%1], 16;" \
        :: "r"(dst), "l"(src) : "memory")
#define CP_COMMIT() asm volatile("cp.async.commit_group;" ::: "memory")
#define CP_WAIT2()  asm volatile("cp.async.wait_group 2;" ::: "memory")
#define CP_WAIT0()  asm volatile("cp.async.wait_group 0;" ::: "memory")

__device__ __forceinline__ void ldsm4(uint32_t& r0, uint32_t& r1,
                                      uint32_t& r2, uint32_t& r3,
                                      uint32_t addr) {
    asm volatile("ldmatrix.sync.aligned.m8n8.x4.shared.b16 {%0,%1,%2,%3}, [%4];"
        : "=r"(r0), "=r"(r1), "=r"(r2), "=r"(r3) : "r"(addr));
}

// ---------------------------------------------------------------------------
// 128x128 NT tf32 GEMM, inputs pre-rounded to tf32 in gmem.
// writeMode: 0 = C[i,j]; 1 = rounded C[i,j]; 2 = rounded transposed C[j][i].
// ---------------------------------------------------------------------------
__device__ __forceinline__ void gemm_tile_body(
    const float* __restrict__ A, int lda,
    const float* __restrict__ B, int ldb,
    float* __restrict__ C, int ldc,
    const float* __restrict__ bias,
    float alpha, int K, int bm, int bn, int writeMode)
{
    extern __shared__ uint32_t sm[];
    uint32_t* Asw = sm;                       // [NSTAGE][128][APAD]
    uint32_t* Bsw = sm + NSTAGE * STG_W;

    const int tid  = threadIdx.x;
    const int lane = tid & 31;
    const int warp = tid >> 5;
    const int wm   = (warp >> 1) * 32;
    const int wn   = (warp & 1) * 64;
    const int gid  = lane >> 2;
    const int tig  = lane & 3;

    const int prow = tid & 127;
    const int pkc  = (tid >> 7) * 8;
    const float* Ap = A + (size_t)(bm + prow) * lda + pkc;
    const float* Bp = B + (size_t)(bn + prow) * ldb + pkc;

    const uint32_t aBase = (uint32_t)__cvta_generic_to_shared(Asw)
                         + (uint32_t)(prow * APAD + pkc) * 4u;
    const uint32_t bBase = (uint32_t)__cvta_generic_to_shared(Bsw)
                         + (uint32_t)(prow * APAD + pkc) * 4u;

    // ldmatrix per-thread source-row addresses.
    // A pattern: row-block bit = (lane>>3)&1, k-half bit = (lane>>4)&1.
    const int aRow = (lane & 7) + ((lane >> 3) & 1) * 8;
    const int aKh  = ((lane >> 4) & 1) * 4;
    const uint32_t aFragBase = (uint32_t)__cvta_generic_to_shared(Asw)
        + (uint32_t)(((wm + aRow) * APAD) + aKh) * 4u;
    // B pattern: k-half bit = (lane>>3)&1, ni-pair-half bit = (lane>>4)&1.
    const int bRow = (lane & 7) + ((lane >> 4) & 1) * 8;
    const int bKh  = ((lane >> 3) & 1) * 4;
    const uint32_t bFragBase = (uint32_t)__cvta_generic_to_shared(Bsw)
        + (uint32_t)(((wn + bRow) * APAD) + bKh) * 4u;

    float acc[2][8][4];
#pragma unroll
    for (int mi = 0; mi < 2; mi++)
#pragma unroll
        for (int ni = 0; ni < 8; ni++)
#pragma unroll
            for (int r = 0; r < 4; r++) acc[mi][ni][r] = 0.0f;

    const int nsteps = K / 16;

#pragma unroll
    for (int s = 0; s < NSTAGE - 1; s++) {
        const uint32_t ad = aBase + (uint32_t)(s * STG_W) * 4u;
        const uint32_t bd = bBase + (uint32_t)(s * STG_W) * 4u;
        CP16(ad,      Ap + s * 16);
        CP16(ad + 16, Ap + s * 16 + 4);
        CP16(bd,      Bp + s * 16);
        CP16(bd + 16, Bp + s * 16 + 4);
        CP_COMMIT();
    }

#pragma unroll 1
    for (int step = 0; step < nsteps; step++) {
        const int cur = step & (NSTAGE - 1);
        CP_WAIT2();
        __syncthreads();

        const uint32_t aF = aFragBase + (uint32_t)(cur * STG_W) * 4u;
        const uint32_t bF = bFragBase + (uint32_t)(cur * STG_W) * 4u;

#pragma unroll
        for (int kk = 0; kk < 2; kk++) {
            const uint32_t kOff = (uint32_t)(kk * 8) * 4u;  // kb*4 bytes
            uint32_t af[2][4];
#pragma unroll
            for (int mi = 0; mi < 2; mi++)
                ldsm4(af[mi][0], af[mi][1], af[mi][2], af[mi][3],
                      aF + kOff + (uint32_t)(mi * 16 * APAD) * 4u);
            uint32_t bf[8][2];
#pragma unroll
            for (int j = 0; j < 4; j++) {
                ldsm4(bf[2*j][0], bf[2*j][1], bf[2*j+1][0], bf[2*j+1][1],
                      bF + kOff + (uint32_t)(j * 16 * APAD) * 4u);
            }
#pragma unroll
            for (int mi = 0; mi < 2; mi++)
#pragma unroll
                for (int ni = 0; ni < 8; ni++) {
                    asm("mma.sync.aligned.m16n8k8.row.col.f32.tf32.tf32.f32 "
                        "{%0,%1,%2,%3}, {%4,%5,%6,%7}, {%8,%9}, {%0,%1,%2,%3};"
                        : "+f"(acc[mi][ni][0]), "+f"(acc[mi][ni][1]),
                          "+f"(acc[mi][ni][2]), "+f"(acc[mi][ni][3])
                        : "r"(af[mi][0]), "r"(af[mi][1]),
                          "r"(af[mi][2]), "r"(af[mi][3]),
                          "r"(bf[ni][0]), "r"(bf[ni][1]));
                }
        }

        const int pf = step + NSTAGE - 1;
        if (pf < nsteps) {
            const int ps = pf & (NSTAGE - 1);
            const uint32_t ad = aBase + (uint32_t)(ps * STG_W) * 4u;
            const uint32_t bd = bBase + (uint32_t)(ps * STG_W) * 4u;
            CP16(ad,      Ap + pf * 16);
            CP16(ad + 16, Ap + pf * 16 + 4);
            CP16(bd,      Bp + pf * 16);
            CP16(bd + 16, Bp + pf * 16 + 4);
        }
        CP_COMMIT();
    }
    CP_WAIT0();

    // epilogue
#pragma unroll
    for (int mi = 0; mi < 2; mi++) {
        const int r0 = bm + wm + mi * 16 + gid;
#pragma unroll
        for (int ni = 0; ni < 8; ni++) {
            const int c0 = bn + wn + ni * 8 + tig * 2;
            float bx = 0.0f, by = 0.0f;
            if (bias) { bx = bias[c0]; by = bias[c0 + 1]; }
            float2 v0, v1;
            v0.x = alpha * acc[mi][ni][0] + bx;
            v0.y = alpha * acc[mi][ni][1] + by;
            v1.x = alpha * acc[mi][ni][2] + bx;
            v1.y = alpha * acc[mi][ni][3] + by;
            if (writeMode == 0) {
                *(float2*)(C + (size_t)r0 * ldc + c0)       = v0;
                *(float2*)(C + (size_t)(r0 + 8) * ldc + c0) = v1;
            } else if (writeMode == 1) {
                v0.x = roundtf(v0.x); v0.y = roundtf(v0.y);
                v1.x = roundtf(v1.x); v1.y = roundtf(v1.y);
                *(float2*)(C + (size_t)r0 * ldc + c0)       = v0;
                *(float2*)(C + (size_t)(r0 + 8) * ldc + c0) = v1;
            } else {
                C[(size_t)(c0    ) * ldc + r0    ] = roundtf(v0.x);
                C[(size_t)(c0 + 1) * ldc + r0    ] = roundtf(v0.y);
                C[(size_t)(c0    ) * ldc + r0 + 8] = roundtf(v1.x);
                C[(size_t)(c0 + 1) * ldc + r0 + 8] = roundtf(v1.y);
            }
        }
    }
}

__global__ __launch_bounds__(256, 2) void mma_gemm(
    const float* __restrict__ A, int lda, long zA,
    const float* __restrict__ B, int ldb, long zB,
    float* __restrict__ C, int ldc, long zC,
    const float* __restrict__ bias, long zBias,
    float alpha, int K, int writeMode)
{
    A += (long)blockIdx.z * zA;
    B += (long)blockIdx.z * zB;
    C += (long)blockIdx.z * zC;
    if (bias) bias += (long)blockIdx.z * zBias;
    gemm_tile_body(A, lda, B, ldb, C, ldc, bias, alpha, K,
                   blockIdx.y * 128, blockIdx.x * 128, writeMode);
}

// Dense projection launch: 128 Q tiles, 24 K tiles, 24 V tiles = 176 CTAs.
__global__ __launch_bounds__(256, 2) void proj3_gemm(
    const float* __restrict__ tn, const float* __restrict__ vn,
    const float* __restrict__ Wq, const float* __restrict__ Wk,
    const float* __restrict__ Wv,
    const float* __restrict__ bq, const float* __restrict__ bk,
    const float* __restrict__ bv,
    float* __restrict__ q, float* __restrict__ k, float* __restrict__ vt)
{
    const int idx = blockIdx.x;
    int z, local;
    if (idx < 128)      { z = 0; local = idx; }
    else if (idx < 152) { z = 1; local = idx - 128; }
    else                { z = 2; local = idx - 152; }
    const int bn = (local & 3) * 128;
    const int bm = (local >> 2) * 128;
    const float* A = (z == 0) ? tn : vn;
    const float* B = (z == 0) ? Wq : (z == 1) ? Wk : Wv;
    const float* bias = (z == 0) ? bq : (z == 1) ? bk : bv;
    if (z == 2) {
        gemm_tile_body(A, EMBED, B, EMBED, vt, VTOK, bias, 1.0f, EMBED,
                       bm, bn, 2);
    } else {
        float* C = (z == 0) ? q : k;
        gemm_tile_body(A, EMBED, B, EMBED, C, EMBED, bias, 1.0f, EMBED,
                       bm, bn, 1);
    }
}

// ---------------------------------------------------------------------------
__global__ __launch_bounds__(256) void roundw_kernel(
    const float* __restrict__ w0, const float* __restrict__ w1,
    const float* __restrict__ w2, const float* __restrict__ w3,
    const float* __restrict__ w4,
    float* __restrict__ o0, float* __restrict__ o1,
    float* __restrict__ o2, float* __restrict__ o3,
    float* __restrict__ o4)
{
    const int i = blockIdx.x * 256 + threadIdx.x;
    const int z = blockIdx.y;
    const float* w = (z == 0) ? w0 : (z == 1) ? w1 : (z == 2) ? w2
                   : (z == 3) ? w3 : w4;
    float* o = (z == 0) ? o0 : (z == 1) ? o1 : (z == 2) ? o2
             : (z == 3) ? o3 : o4;
    float4 x = *(const float4*)(w + i * 4);
    float4 y;
    y.x = roundtf(x.x); y.y = roundtf(x.y);
    y.z = roundtf(x.z); y.w = roundtf(x.w);
    *(float4*)(o + i * 4) = y;
}

// ---------------------------------------------------------------------------
__global__ __launch_bounds__(128) void ln_kernel(
    const float* __restrict__ x, const float* __restrict__ addx,
    const float* __restrict__ g, const float* __restrict__ b,
    float* __restrict__ out, float* __restrict__ out_r, int round_main)
{
    const int row = blockIdx.x;
    const int t = threadIdx.x;
    const float* xr = x + (size_t)row * EMBED;

    float v[4];
#pragma unroll
    for (int i = 0; i < 4; i++) {
        float val = xr[t + i * 128];
        if (addx) val += addx[(size_t)row * EMBED + t + i * 128];
        v[i] = val;
    }
    float s  = v[0] + v[1] + v[2] + v[3];
    float s2 = v[0]*v[0] + v[1]*v[1] + v[2]*v[2] + v[3]*v[3];
#pragma unroll
    for (int o = 16; o > 0; o >>= 1) {
        s  += __shfl_xor_sync(0xffffffffu, s,  o);
        s2 += __shfl_xor_sync(0xffffffffu, s2, o);
    }
    __shared__ float ss[4], ss2[4];
    const int w = t >> 5, l = t & 31;
    if (l == 0) { ss[w] = s; ss2[w] = s2; }
    __syncthreads();
    s  = ss[0] + ss[1] + ss[2] + ss[3];
    s2 = ss2[0] + ss2[1] + ss2[2] + ss2[3];

    const float mu   = s * (1.0f / EMBED);
    const float var  = s2 * (1.0f / EMBED) - mu * mu;
    const float rstd = rsqrtf(var + 1e-5f);
#pragma unroll
    for (int i = 0; i < 4; i++) {
        const int c = t + i * 128;
        float y = (v[i] - mu) * rstd * g[c] + b[c];
        out[(size_t)row * EMBED + c] = round_main ? roundtf(y) : y;
        if (out_r) out_r[(size_t)row * EMBED + c] = roundtf(y);
    }
}

// ---------------------------------------------------------------------------
__global__ __launch_bounds__(256) void softmax_kernel(float* __restrict__ S, int ngroups)
{
    const int g = blockIdx.x * blockDim.x + threadIdx.x;
    if (g >= ngroups) return;
    float* p = S + (size_t)g * FR;
    float v[FR];
    float m = -3.0e38f;
#pragma unroll
    for (int i = 0; i < FR; i++) { v[i] = p[i]; m = fmaxf(m, v[i]); }
    float sum = 0.0f;
#pragma unroll
    for (int i = 0; i < FR; i++) { v[i] = __expf(v[i] - m); sum += v[i]; }
    const float inv = 1.0f / sum;
#pragma unroll
    for (int i = 0; i < FR; i++) p[i] = roundtf(v[i] * inv);
}

// ---------------------------------------------------------------------------
extern "C" void kernel_launch(void* const* d_in, const int* in_sizes, int n_in,
                              void* d_out, int out_size)
{
    const float* text  = (const float*)d_in[0];
    const float* video = (const float*)d_in[1];
    const float* ln1_g = (const float*)d_in[2];
    const float* ln1_b = (const float*)d_in[3];
    const float* Wq = (const float*)d_in[4];
    const float* bq = (const float*)d_in[5];
    const float* Wk = (const float*)d_in[6];
    const float* bk = (const float*)d_in[7];
    const float* Wv = (const float*)d_in[8];
    const float* bv = (const float*)d_in[9];
    const float* Wo = (const float*)d_in[10];
    const float* bo = (const float*)d_in[11];
    const float* Wl = (const float*)d_in[12];
    const float* bl = (const float*)d_in[13];
    const float* ln2_g = (const float*)d_in[14];
    const float* ln2_b = (const float*)d_in[15];
    const float* ln3_g = (const float*)d_in[16];
    const float* ln3_b = (const float*)d_in[17];
    float* out = (float*)d_out;

    cudaFuncSetAttribute(mma_gemm,
        cudaFuncAttributeMaxDynamicSharedMemorySize, SMEM_BYTES);
    cudaFuncSetAttribute(proj3_gemm,
        cudaFuncAttributeMaxDynamicSharedMemorySize, SMEM_BYTES);

    float *tn, *vn, *q, *k, *vt, *s, *attn, *opre, *o, *orr, *lin;
    float *wqr, *wkr, *wvr, *wor, *wlr;
    cudaGetSymbolAddress((void**)&tn,   g_tn);
    cudaGetSymbolAddress((void**)&vn,   g_vn);
    cudaGetSymbolAddress((void**)&q,    g_q);
    cudaGetSymbolAddress((void**)&k,    g_k);
    cudaGetSymbolAddress((void**)&vt,   g_vt);
    cudaGetSymbolAddress((void**)&s,    g_s);
    cudaGetSymbolAddress((void**)&attn, g_attn);
    cudaGetSymbolAddress((void**)&opre, g_opre);
    cudaGetSymbolAddress((void**)&o,    g_o);
    cudaGetSymbolAddress((void**)&orr,  g_or);
    cudaGetSymbolAddress((void**)&lin,  g_lin);
    cudaGetSymbolAddress((void**)&wqr,  g_wqr);
    cudaGetSymbolAddress((void**)&wkr,  g_wkr);
    cudaGetSymbolAddress((void**)&wvr,  g_wvr);
    cudaGetSymbolAddress((void**)&wor,  g_wor);
    cudaGetSymbolAddress((void**)&wlr,  g_wlr);

    // 0) round all weights to tf32 (overlaps LN1)
    roundw_kernel<<<dim3(EMBED*EMBED/1024, 5), 256>>>(
        Wq, Wk, Wv, Wo, Wl, wqr, wkr, wvr, wor, wlr);

    // 1) shared LN1 (outputs tf32-rounded)
    ln_kernel<<<TTOK, 128>>>(text,  nullptr, ln1_g, ln1_b, tn, nullptr, 1);
    ln_kernel<<<VTOK, 128>>>(video, nullptr, ln1_g, ln1_b, vn, nullptr, 1);

    // 2) Q/K/V projections (V written transposed into vt), 176 CTAs
    proj3_gemm<<<176, 256, SMEM_BYTES>>>(
        tn, vn, wqr, wkr, wvr, bq, bk, bv, q, k, vt);

    // 3) logits: S_h = Q_h @ K_h^T / 16 (384 CTAs)
    mma_gemm<<<dim3(6, 32, 2), 256, SMEM_BYTES>>>(
        q, EMBED, HDIM, k, EMBED, HDIM,
        s, VTOK, (long)TTOK * VTOK, nullptr, 0, 1.0f / 16.0f, HDIM, 0);

    // 4) per-video frame softmax (rounds output)
    softmax_kernel<<<(HEADS * TTOK * NV + 255) / 256, 256>>>(s, HEADS * TTOK * NV);

    // 5) attn_h = P_h @ V_h / 64 (rounded out; 128 CTAs)
    mma_gemm<<<dim3(2, 32, 2), 256, SMEM_BYTES>>>(
        s, VTOK, (long)TTOK * VTOK, vt, VTOK, (long)HDIM * VTOK,
        attn, EMBED, HDIM, nullptr, 0, 1.0f / 64.0f, VTOK, 1);

    // 6) output projection + LN2 (o full + rounded copy; 128 CTAs)
    mma_gemm<<<dim3(4, 32, 1), 256, SMEM_BYTES>>>(
        attn, EMBED, 0, wor, EMBED, 0, opre, EMBED, 0, bo, 0, 1.0f, EMBED, 0);
    ln_kernel<<<TTOK, 128>>>(opre, nullptr, ln2_g, ln2_b, o, orr, 0);

    // 7) linear + residual + LN3 (128 CTAs)
    mma_gemm<<<dim3(4, 32, 1), 256, SMEM_BYTES>>>(
        orr, EMBED, 0, wlr, EMBED, 0, lin, EMBED, 0, bl, 0, 1.0f, EMBED, 0);
    ln_kernel<<<TTOK, 128>>>(o, lin, ln3_g, ln3_b, out, nullptr, 0);
}